// round 16
// baseline (speedup 1.0000x reference)
#include <cuda_runtime.h>
#include <cuda_bf16.h>
#include <math.h>
#include <float.h>

#define Bq    4
#define Tq    12
#define Nq    200
#define Cq    64
#define ATTq  128
#define OUTFq 128
#define PREDq 12
#define Mq    600
#define BW0   40
#define BW1   32

enum { F_RELU = 1, F_RELUB = 2, F_SIGMOID = 4 };

__device__ float g_cur  [BW0 * Mq * Cq];
__device__ float g_qkv  [BW0 * Mq * 3 * ATTq];
__device__ float g_nA   [Mq * Cq];
__device__ float g_nB   [Mq * Cq];
__device__ float g_adj  [Mq * Mq];
__device__ float g_cand0[BW0 * Nq * Cq];
__device__ float g_cand1[BW1 * Nq * Cq];

__device__ __forceinline__ float2 ffma2(float2 a, float2 b, float2 c)
{
    float2 d;
    asm("fma.rn.f32x2 %0, %1, %2, %3;"
        : "=l"(reinterpret_cast<unsigned long long&>(d))
        : "l"(reinterpret_cast<unsigned long long&>(a)),
          "l"(reinterpret_cast<unsigned long long&>(b)),
          "l"(reinterpret_cast<unsigned long long&>(c)));
    return d;
}

// ---------------------------------------------------------------------------
// Generic fast GEMM — exact R8 version (used for qkv projection).
// ---------------------------------------------------------------------------
template<bool TB>
__global__ void __launch_bounds__(128, 3)
gemm_fast(const float* __restrict__ A, int lda, long long aBS,
          const float* __restrict__ B, int ldb, long long bBS,
          float* __restrict__ Cm, int ldc, long long cBS,
          int M, int N, int K,
          const float* __restrict__ bias, float scale, int flags)
{
    __shared__ __align__(16) float  As[2][16][128];
    __shared__ __align__(16) float2 Bs[2][16][8][8];

    A  += (long long)blockIdx.z * aBS;
    B  += (long long)blockIdx.z * bBS;
    Cm += (long long)blockIdx.z * cBS;

    const int m0 = blockIdx.y * 128, n0 = blockIdx.x * 64;
    const int tid = threadIdx.x;
    const int tm = tid >> 3, tn = tid & 7;

    float2 acc[4][8];
    #pragma unroll
    for (int i = 0; i < 4; ++i)
        #pragma unroll
        for (int j = 0; j < 8; ++j) acc[i][j] = make_float2(0.f, 0.f);

    const int nk = (K + 15) >> 4;
    const bool relub = (flags & F_RELUB);
    float va[16], vb[8];

    auto loadA = [&](int k0) {
        const int gm = m0 + tid;
        if (gm < M) {
            const float* p = A + (long long)gm * lda + k0;
            if (k0 + 16 <= K) {
                const float4* q = (const float4*)p;
                float4 t0 = q[0], t1 = q[1], t2 = q[2], t3 = q[3];
                va[0]=t0.x; va[1]=t0.y; va[2]=t0.z; va[3]=t0.w;
                va[4]=t1.x; va[5]=t1.y; va[6]=t1.z; va[7]=t1.w;
                va[8]=t2.x; va[9]=t2.y; va[10]=t2.z; va[11]=t2.w;
                va[12]=t3.x; va[13]=t3.y; va[14]=t3.z; va[15]=t3.w;
            } else {
                #pragma unroll
                for (int t = 0; t < 16; ++t)
                    va[t] = (k0 + t < K) ? p[t] : 0.f;
            }
        } else {
            #pragma unroll
            for (int t = 0; t < 16; ++t) va[t] = 0.f;
        }
    };
    auto loadB = [&](int k0) {
        if (!TB) {
            const int kb = tid >> 3, nb = tid & 7;
            const int gk = k0 + kb, gn0 = n0 + nb * 8;
            if (gk < K) {
                const float* p = B + (long long)gk * ldb + gn0;
                if (gn0 + 8 <= N) {
                    const float4* q = (const float4*)p;
                    float4 t0 = q[0], t1 = q[1];
                    vb[0]=t0.x; vb[1]=t0.y; vb[2]=t0.z; vb[3]=t0.w;
                    vb[4]=t1.x; vb[5]=t1.y; vb[6]=t1.z; vb[7]=t1.w;
                } else {
                    #pragma unroll
                    for (int j = 0; j < 8; ++j)
                        vb[j] = (gn0 + j < N) ? p[j] : 0.f;
                }
            } else {
                #pragma unroll
                for (int j = 0; j < 8; ++j) vb[j] = 0.f;
            }
        } else {
            const int nl = tid >> 1, kh = (tid & 1) * 8;
            const int gn = n0 + nl, gk0 = k0 + kh;
            if (gn < N) {
                const float* p = B + (long long)gn * ldb + gk0;
                if (gk0 + 8 <= K) {
                    const float4* q = (const float4*)p;
                    float4 t0 = q[0], t1 = q[1];
                    vb[0]=t0.x; vb[1]=t0.y; vb[2]=t0.z; vb[3]=t0.w;
                    vb[4]=t1.x; vb[5]=t1.y; vb[6]=t1.z; vb[7]=t1.w;
                } else {
                    #pragma unroll
                    for (int t = 0; t < 8; ++t)
                        vb[t] = (gk0 + t < K) ? p[t] : 0.f;
                }
            } else {
                #pragma unroll
                for (int t = 0; t < 8; ++t) vb[t] = 0.f;
            }
        }
    };
    auto storeA = [&](int buf) {
        #pragma unroll
        for (int t = 0; t < 16; ++t) As[buf][t][tid] = va[t];
    };
    auto storeB = [&](int buf) {
        if (!TB) {
            const int kb = tid >> 3, nb = tid & 7;
            #pragma unroll
            for (int j = 0; j < 8; ++j) {
                float v = vb[j];
                if (relub) v = fmaxf(v, 0.f);
                Bs[buf][kb][j][nb] = make_float2(v, v);
            }
        } else {
            const int nl = tid >> 1, kh = (tid & 1) * 8;
            const int jj = nl & 7, tt = nl >> 3;
            #pragma unroll
            for (int t = 0; t < 8; ++t) {
                float v = vb[t];
                if (relub) v = fmaxf(v, 0.f);
                Bs[buf][kh + t][jj][tt] = make_float2(v, v);
            }
        }
    };

    int buf = 0;
    loadA(0); loadB(0);
    storeA(0); storeB(0);
    __syncthreads();

    for (int t = 0; t < nk; ++t) {
        if (t + 1 < nk) { loadA((t + 1) * 16); loadB((t + 1) * 16); }
        #pragma unroll
        for (int kk = 0; kk < 16; ++kk) {
            const float4* ap = (const float4*)(&As[buf][kk][0]) + tm * 2;
            float4 a0 = ap[0], a1 = ap[1];
            float2 a2[4];
            a2[0] = make_float2(a0.x, a0.y);
            a2[1] = make_float2(a0.z, a0.w);
            a2[2] = make_float2(a1.x, a1.y);
            a2[3] = make_float2(a1.z, a1.w);
            #pragma unroll
            for (int j = 0; j < 8; ++j) {
                float2 b2 = Bs[buf][kk][j][tn];
                #pragma unroll
                for (int i = 0; i < 4; ++i)
                    acc[i][j] = ffma2(a2[i], b2, acc[i][j]);
            }
        }
        if (t + 1 < nk) { buf ^= 1; storeA(buf); storeB(buf); }
        __syncthreads();
    }

    auto epi = [&](float v, int gn) {
        v *= scale;
        if (bias) v += bias[gn];
        if (flags & F_RELU) v = fmaxf(v, 0.f);
        if (flags & F_SIGMOID) v = 1.f / (1.f + __expf(-v));
        return v;
    };

    const int gn0 = n0 + tn * 8;
    const bool interior = (gn0 + 8 <= N) && (m0 + tm * 8 + 8 <= M);
    if (interior) {
        #pragma unroll
        for (int i = 0; i < 4; ++i)
            #pragma unroll
            for (int half = 0; half < 2; ++half) {
                const int gm = m0 + tm * 8 + 2 * i + half;
                float r[8];
                #pragma unroll
                for (int j = 0; j < 8; ++j)
                    r[j] = epi(half ? acc[i][j].y : acc[i][j].x, gn0 + j);
                float4* q = (float4*)(Cm + (long long)gm * ldc + gn0);
                q[0] = make_float4(r[0], r[1], r[2], r[3]);
                q[1] = make_float4(r[4], r[5], r[6], r[7]);
            }
    } else {
        #pragma unroll
        for (int i = 0; i < 4; ++i)
            #pragma unroll
            for (int half = 0; half < 2; ++half) {
                const int gm = m0 + tm * 8 + 2 * i + half;
                if (gm >= M) continue;
                #pragma unroll
                for (int j = 0; j < 8; ++j) {
                    const int gn = gn0 + j;
                    if (gn >= N) continue;
                    Cm[(long long)gm * ldc + gn] =
                        epi(half ? acc[i][j].y : acc[i][j].x, gn);
                }
            }
    }
}

// ---------------------------------------------------------------------------
// Fused output tail — exact R15 version.
// ---------------------------------------------------------------------------
__global__ void __launch_bounds__(128, 3)
gemm_tail(const float* __restrict__ h,
          const float* __restrict__ Wo,
          const float* __restrict__ bo,
          float* __restrict__ out)
{
    const int M = Bq * Nq, N = OUTFq, K = 8 * Cq;

    __shared__ __align__(16) float  As[2][16][128];
    __shared__ __align__(16) float2 Bs[2][16][8][8];

    const int m0 = blockIdx.y * 128, n0 = blockIdx.x * 64;
    const int tid = threadIdx.x;
    const int tm = tid >> 3, tn = tid & 7;

    float2 acc[4][8];
    #pragma unroll
    for (int i = 0; i < 4; ++i)
        #pragma unroll
        for (int j = 0; j < 8; ++j) acc[i][j] = make_float2(0.f, 0.f);

    const int nk = K / 16;
    float va[16], vb[8];

    const int gm_a = m0 + tid;
    const int ab = gm_a / Nq, an = gm_a % Nq;

    auto loadA = [&](int k0) {
        if (gm_a < M) {
            const int t = k0 >> 6, f0 = k0 & 63;
            const float4* q = (const float4*)
                (h + (((long long)(ab * 8 + t) * Nq + an) << 6) + f0);
            float4 t0 = q[0], t1 = q[1], t2 = q[2], t3 = q[3];
            va[0]=t0.x; va[1]=t0.y; va[2]=t0.z; va[3]=t0.w;
            va[4]=t1.x; va[5]=t1.y; va[6]=t1.z; va[7]=t1.w;
            va[8]=t2.x; va[9]=t2.y; va[10]=t2.z; va[11]=t2.w;
            va[12]=t3.x; va[13]=t3.y; va[14]=t3.z; va[15]=t3.w;
        } else {
            #pragma unroll
            for (int t = 0; t < 16; ++t) va[t] = 0.f;
        }
    };
    auto loadB = [&](int k0) {
        const int kb = tid >> 3, nb = tid & 7;
        const float* p = Wo + (long long)(k0 + kb) * N + n0 + nb * 8;
        const float4* q = (const float4*)p;
        float4 t0 = q[0], t1 = q[1];
        vb[0]=t0.x; vb[1]=t0.y; vb[2]=t0.z; vb[3]=t0.w;
        vb[4]=t1.x; vb[5]=t1.y; vb[6]=t1.z; vb[7]=t1.w;
    };
    auto storeA = [&](int buf) {
        #pragma unroll
        for (int t = 0; t < 16; ++t) As[buf][t][tid] = va[t];
    };
    auto storeB = [&](int buf) {
        const int kb = tid >> 3, nb = tid & 7;
        #pragma unroll
        for (int j = 0; j < 8; ++j)
            Bs[buf][kb][j][nb] = make_float2(vb[j], vb[j]);
    };

    int buf = 0;
    loadA(0); loadB(0);
    storeA(0); storeB(0);
    __syncthreads();

    for (int t = 0; t < nk; ++t) {
        if (t + 1 < nk) { loadA((t + 1) * 16); loadB((t + 1) * 16); }
        #pragma unroll
        for (int kk = 0; kk < 16; ++kk) {
            const float4* ap = (const float4*)(&As[buf][kk][0]) + tm * 2;
            float4 a0 = ap[0], a1 = ap[1];
            float2 a2[4];
            a2[0] = make_float2(a0.x, a0.y);
            a2[1] = make_float2(a0.z, a0.w);
            a2[2] = make_float2(a1.x, a1.y);
            a2[3] = make_float2(a1.z, a1.w);
            #pragma unroll
            for (int j = 0; j < 8; ++j) {
                float2 b2 = Bs[buf][kk][j][tn];
                #pragma unroll
                for (int i = 0; i < 4; ++i)
                    acc[i][j] = ffma2(a2[i], b2, acc[i][j]);
            }
        }
        if (t + 1 < nk) { buf ^= 1; storeA(buf); storeB(buf); }
        __syncthreads();
    }

    const int gn0 = n0 + tn * 8;
    #pragma unroll
    for (int i = 0; i < 4; ++i)
        #pragma unroll
        for (int half = 0; half < 2; ++half) {
            const int gm = m0 + tm * 8 + 2 * i + half;
            if (gm >= M) continue;
            float r[8];
            #pragma unroll
            for (int j = 0; j < 8; ++j) {
                float v = (half ? acc[i][j].y : acc[i][j].x) + bo[gn0 + j];
                r[j] = fmaxf(v, 0.f);
            }
            const float4 v0 = make_float4(r[0], r[1], r[2], r[3]);
            const float4 v1 = make_float4(r[4], r[5], r[6], r[7]);
            const int b = gm / Nq, n = gm % Nq;
            float* obase = out + ((long long)b * PREDq * Nq + n) * OUTFq + gn0;
            #pragma unroll
            for (int p = 0; p < PREDq; ++p) {
                float4* q = (float4*)(obase + (long long)p * Nq * OUTFq);
                q[0] = v0; q[1] = v1;
            }
        }
}

// ---------------------------------------------------------------------------
// Fused flash attention — exact R8/R14 kernel body (pointers pre-offset by
// the caller for bw-half pipelining; blockIdx.y is the local window index).
// ---------------------------------------------------------------------------
#define RQT 96
#define FA_SMEM_BYTES (23424 * 4)

__global__ void __launch_bounds__(256, 2)
flash_attn(const float* __restrict__ qkv,
           const float* __restrict__ adj,
           const float* __restrict__ Wlin,
           const float* __restrict__ blin,
           float* __restrict__ curo,
           float* __restrict__ cand,
           float scale, int candmode)
{
    extern __shared__ float sm[];
    float*  Qs  = sm;
    float2* Ks  = (float2*)(sm + 12544);
    float2* Vs  = (float2*)(sm + 12544);
    float*  Ps  = sm + 16768;
    float*  At  = sm;
    float*  Wl  = sm + 12544;
    float*  m_s  = sm + 23040;
    float*  z_s  = m_s + RQT;
    float*  sa_s = z_s + RQT;
    float*  f_s  = sa_s + RQT;

    const int tid = threadIdx.x;
    const int bw  = blockIdx.y;
    const int r0  = blockIdx.x * RQT;
    const int tmA = tid >> 4, tnA = tid & 15;
    const int twB = tid >> 5, tnB = tid & 31;

    const float* qb = qkv + (long long)bw * Mq * 384;

    #pragma unroll
    for (int i = tid; i < 96 * 32; i += 256) {
        const int mq = i >> 5;
        const int kq = (i & 31) << 2;
        float4 v = make_float4(0.f, 0.f, 0.f, 0.f);
        if (r0 + mq < Mq)
            v = *(const float4*)(qb + (long long)(r0 + mq) * 384 + kq);
        Qs[(kq + 0) * 98 + mq] = v.x;
        Qs[(kq + 1) * 98 + mq] = v.y;
        Qs[(kq + 2) * 98 + mq] = v.z;
        Qs[(kq + 3) * 98 + mq] = v.w;
    }
    if (tid < RQT) { m_s[tid] = -FLT_MAX; z_s[tid] = 0.f; sa_s[tid] = 0.f; }

    float2 acc[6][4];
    #pragma unroll
    for (int i = 0; i < 6; ++i)
        #pragma unroll
        for (int j = 0; j < 4; ++j) acc[i][j] = make_float2(0.f, 0.f);

    const int bn = tid >> 2;
    const int kh = (tid & 3) << 2;

    __syncthreads();

    for (int ch = 0; ch < 10; ++ch) {
        const int n0 = ch * 64;

        float2 sA[3][4];
        #pragma unroll
        for (int p = 0; p < 3; ++p)
            #pragma unroll
            for (int j = 0; j < 4; ++j) sA[p][j] = make_float2(0.f, 0.f);

        {
            const int gn = n0 + bn;
            float4 kv = (gn < Mq)
                ? *(const float4*)(qb + (long long)gn * 384 + 128 + kh)
                : make_float4(0.f, 0.f, 0.f, 0.f);
            Ks[(kh + 0) * 66 + bn] = make_float2(kv.x, kv.x);
            Ks[(kh + 1) * 66 + bn] = make_float2(kv.y, kv.y);
            Ks[(kh + 2) * 66 + bn] = make_float2(kv.z, kv.z);
            Ks[(kh + 3) * 66 + bn] = make_float2(kv.w, kv.w);
        }
        __syncthreads();

        #pragma unroll
        for (int s = 0; s < 8; ++s) {
            float4 kv = make_float4(0.f, 0.f, 0.f, 0.f);
            if (s < 7) {
                const int gn = n0 + bn;
                if (gn < Mq)
                    kv = *(const float4*)(qb + (long long)gn * 384 + 128
                                          + (s + 1) * 16 + kh);
            }
            const float2* kbuf = Ks + (s & 1) * (16 * 66);
            const int kq0 = s * 16;
            #pragma unroll
            for (int kk = 0; kk < 16; ++kk) {
                const float2* ap = (const float2*)(Qs + (kq0 + kk) * 98 + 6 * tmA);
                const float2 a0 = ap[0], a1 = ap[1], a2 = ap[2];
                #pragma unroll
                for (int j = 0; j < 4; ++j) {
                    const float2 b = kbuf[kk * 66 + tnA + 16 * j];
                    sA[0][j] = ffma2(a0, b, sA[0][j]);
                    sA[1][j] = ffma2(a1, b, sA[1][j]);
                    sA[2][j] = ffma2(a2, b, sA[2][j]);
                }
            }
            if (s < 7) {
                float2* kdst = Ks + ((s + 1) & 1) * (16 * 66);
                kdst[(kh + 0) * 66 + bn] = make_float2(kv.x, kv.x);
                kdst[(kh + 1) * 66 + bn] = make_float2(kv.y, kv.y);
                kdst[(kh + 2) * 66 + bn] = make_float2(kv.z, kv.z);
                kdst[(kh + 3) * 66 + bn] = make_float2(kv.w, kv.w);
            }
            __syncthreads();
        }

        #pragma unroll
        for (int p = 0; p < 3; ++p) {
            const int r = 6 * tmA + 2 * p;
            float2 sv[4];
            #pragma unroll
            for (int j = 0; j < 4; ++j) {
                const int gn = n0 + tnA + 16 * j;
                if (gn < Mq) {
                    sv[j].x = sA[p][j].x * scale;
                    sv[j].y = sA[p][j].y * scale;
                } else { sv[j].x = -FLT_MAX; sv[j].y = -FLT_MAX; }
            }
            float mxx = fmaxf(fmaxf(sv[0].x, sv[1].x), fmaxf(sv[2].x, sv[3].x));
            float mxy = fmaxf(fmaxf(sv[0].y, sv[1].y), fmaxf(sv[2].y, sv[3].y));
            #pragma unroll
            for (int w = 8; w; w >>= 1) {
                mxx = fmaxf(mxx, __shfl_xor_sync(0xffffffffu, mxx, w));
                mxy = fmaxf(mxy, __shfl_xor_sync(0xffffffffu, mxy, w));
            }
            const float mox = m_s[r], moy = m_s[r + 1];
            const float mnx = fmaxf(mox, mxx), mny = fmaxf(moy, mxy);
            const float fx = __expf(mox - mnx), fy = __expf(moy - mny);

            const int grx = r0 + r, gry = grx + 1;
            float zex = 0.f, zey = 0.f, saex = 0.f, saey = 0.f;
            #pragma unroll
            for (int j = 0; j < 4; ++j) {
                const int gn = n0 + tnA + 16 * j;
                const float ex = __expf(sv[j].x - mnx);
                const float ey = __expf(sv[j].y - mny);
                float ax = 0.f, ay = 0.f;
                if (gn < Mq) {
                    if (grx < Mq) ax = adj[(long long)grx * Mq + gn];
                    if (gry < Mq) ay = adj[(long long)gry * Mq + gn];
                }
                const float px = ex * ax, py = ey * ay;
                zex += ex; zey += ey; saex += px; saey += py;
                *(float2*)&Ps[(tnA + 16 * j) * 98 + r] = make_float2(px, py);
            }
            #pragma unroll
            for (int w = 8; w; w >>= 1) {
                zex  += __shfl_xor_sync(0xffffffffu, zex,  w);
                zey  += __shfl_xor_sync(0xffffffffu, zey,  w);
                saex += __shfl_xor_sync(0xffffffffu, saex, w);
                saey += __shfl_xor_sync(0xffffffffu, saey, w);
            }
            if (tnA == 0) {
                z_s[r]      = z_s[r]      * fx + zex;
                z_s[r + 1]  = z_s[r + 1]  * fy + zey;
                sa_s[r]     = sa_s[r]     * fx + saex;
                sa_s[r + 1] = sa_s[r + 1] * fy + saey;
                m_s[r] = mnx; m_s[r + 1] = mny;
                f_s[r] = fx;  f_s[r + 1] = fy;
            }
        }
        __syncthreads();

        #pragma unroll
        for (int i = 0; i < 6; ++i) {
            const int r = 12 * twB + 2 * i;
            const float2 f2 = *(const float2*)&f_s[r];
            #pragma unroll
            for (int j = 0; j < 4; ++j) {
                acc[i][j].x *= f2.x; acc[i][j].y *= f2.y;
            }
        }

        #pragma unroll
        for (int vs = 0; vs < 4; ++vs) {
            #pragma unroll
            for (int rr = 0; rr < 2; ++rr) {
                const int n = rr * 8 + twB;
                const int gn = n0 + vs * 16 + n;
                #pragma unroll
                for (int s4 = 0; s4 < 4; ++s4) {
                    const int c = tnB + 32 * s4;
                    const float v = (gn < Mq)
                        ? fmaxf(qb[(long long)gn * 384 + 256 + c], 0.f) : 0.f;
                    Vs[n * 132 + tnB + 32 * s4] = make_float2(v, v);
                }
            }
            __syncthreads();
            #pragma unroll
            for (int nn = 0; nn < 16; ++nn) {
                const int n = vs * 16 + nn;
                const float2* prow = (const float2*)&Ps[n * 98 + 12 * twB];
                const float2 p0 = prow[0], p1 = prow[1], p2 = prow[2],
                             p3 = prow[3], p4 = prow[4], p5 = prow[5];
                #pragma unroll
                for (int j = 0; j < 4; ++j) {
                    const float2 b = Vs[nn * 132 + tnB + 32 * j];
                    acc[0][j] = ffma2(p0, b, acc[0][j]);
                    acc[1][j] = ffma2(p1, b, acc[1][j]);
                    acc[2][j] = ffma2(p2, b, acc[2][j]);
                    acc[3][j] = ffma2(p3, b, acc[3][j]);
                    acc[4][j] = ffma2(p4, b, acc[4][j]);
                    acc[5][j] = ffma2(p5, b, acc[5][j]);
                }
            }
            __syncthreads();
        }
    }

    // ---- fused epilogue: cur = att @ Wlin + blin ----
    #pragma unroll
    for (int i = 0; i < 6; ++i) {
        const int r = 12 * twB + 2 * i;
        #pragma unroll
        for (int h = 0; h < 2; ++h) {
            const int row = r + h;
            const float sa = sa_s[row], zz = z_s[row];
            const float inv = (sa > 0.f) ? 1.f / (sa + 1e-8f * zz) : 0.f;
            #pragma unroll
            for (int j = 0; j < 4; ++j) {
                const int c = tnB + 32 * j;
                At[c * 98 + row] = (h ? acc[i][j].y : acc[i][j].x) * inv;
            }
        }
    }
    #pragma unroll
    for (int i = tid; i < 128 * 16; i += 256) {
        const int k = i >> 4;
        const int c4 = (i & 15) << 2;
        const float4 w = *(const float4*)(Wlin + k * 64 + c4);
        Wl[k * 66 + c4 + 0] = w.x;
        Wl[k * 66 + c4 + 1] = w.y;
        Wl[k * 66 + c4 + 2] = w.z;
        Wl[k * 66 + c4 + 3] = w.w;
    }
    __syncthreads();

    {
        const int lane = tid & 31;
        const int c0 = lane * 2;
        const int rbase = 12 * twB;
        float2 o0[6], o1[6];
        #pragma unroll
        for (int p = 0; p < 6; ++p) {
            o0[p] = make_float2(0.f, 0.f);
            o1[p] = make_float2(0.f, 0.f);
        }
        #pragma unroll 4
        for (int k = 0; k < 128; ++k) {
            const float2* arow = (const float2*)(At + k * 98 + rbase);
            const float2 bv = *(const float2*)(Wl + k * 66 + c0);
            const float2 b0 = make_float2(bv.x, bv.x);
            const float2 b1 = make_float2(bv.y, bv.y);
            #pragma unroll
            for (int p = 0; p < 6; ++p) {
                const float2 a = arow[p];
                o0[p] = ffma2(a, b0, o0[p]);
                o1[p] = ffma2(a, b1, o1[p]);
            }
        }
        const float bl0 = blin[c0], bl1 = blin[c0 + 1];
        #pragma unroll
        for (int p = 0; p < 6; ++p) {
            #pragma unroll
            for (int h = 0; h < 2; ++h) {
                const int gq = r0 + rbase + 2 * p + h;
                if (gq >= Mq) continue;
                const float v0 = (h ? o0[p].y : o0[p].x) + bl0;
                const float v1 = (h ? o1[p].y : o1[p].x) + bl1;
                float* cp = curo + ((long long)bw * Mq + gq) * Cq + c0;
                *(float2*)cp = make_float2(v0, v1);
                if (gq >= 2 * Nq) {
                    float* kp = cand + ((long long)(bw * Nq + (gq - 2 * Nq)) * Cq) + c0;
                    if (candmode == 1)
                        *(float2*)kp = make_float2(v0, v1);
                    else {
                        float2 c2 = *(float2*)kp;
                        *(float2*)kp = make_float2(fmaxf(c2.x, v0),
                                                   fmaxf(c2.y, v1));
                    }
                }
            }
        }
    }
}

// ---------------------------------------------------------------------------
// adjacency
// ---------------------------------------------------------------------------
__global__ void __launch_bounds__(256)
adj_rows_kernel(const float* __restrict__ cur,
                const float* __restrict__ Wa,
                const float* __restrict__ Wb,
                float* __restrict__ nA,
                float* __restrict__ nB, int BW)
{
    __shared__ float node_s[4][Cq];
    const int tid = threadIdx.x;
    const int mi = tid >> 6, c = tid & 63;
    const int m = blockIdx.x * 4 + mi;
    float s = 0.f;
    for (int bw = 0; bw < BW; ++bw)
        s += cur[((long long)bw * Mq + m) * Cq + c];
    node_s[mi][c] = s / (float)BW;
    __syncthreads();
    float a = 0.f, b = 0.f;
    #pragma unroll
    for (int k = 0; k < Cq; ++k) {
        const float nv = node_s[mi][k];
        a = fmaf(nv, Wa[k * Cq + c], a);
        b = fmaf(nv, Wb[k * Cq + c], b);
    }
    nA[m * Cq + c] = a;
    nB[m * Cq + c] = b;
}

__global__ void __launch_bounds__(256)
adj_sigmoid(const float* __restrict__ nA, const float* __restrict__ nB,
            float* __restrict__ adj)
{
    __shared__ float a_s[16][Cq];
    __shared__ float b_s[64][Cq + 1];
    const int r0 = blockIdx.y * 16, n0 = blockIdx.x * 64;
    const int tid = threadIdx.x;

    #pragma unroll
    for (int i = tid; i < 16 * Cq; i += 256) {
        const int r = i >> 6, k = i & 63;
        a_s[r][k] = (r0 + r < Mq) ? nA[(r0 + r) * Cq + k] : 0.f;
    }
    #pragma unroll
    for (int i = tid; i < 64 * Cq; i += 256) {
        const int n = i >> 6, k = i & 63;
        b_s[n][k] = (n0 + n < Mq) ? nB[(n0 + n) * Cq + k] : 0.f;
    }
    __syncthreads();

    const int tr = tid >> 6;
    const int tc = tid & 63;
    #pragma unroll
    for (int rr = 0; rr < 4; ++rr) {
        const int r = tr * 4 + rr;
        float s = 0.f;
        #pragma unroll
        for (int k = 0; k < Cq; ++k)
            s = fmaf(a_s[r][k], b_s[tc][k], s);
        const int gr = r0 + r, gn = n0 + tc;
        if (gr < Mq && gn < Mq)
            adj[(long long)gr * Mq + gn] = 1.f / (1.f + __expf(-s * 0.125f));
    }
}

// ---------------------------------------------------------------------------
// Elementwise helpers
// ---------------------------------------------------------------------------
__global__ void build_windows_kernel(const float* __restrict__ src,
                                     const float* __restrict__ temb,
                                     const float* __restrict__ semb,
                                     float* __restrict__ dst,
                                     int nw, int Tt)
{
    const long long total = (long long)Bq * nw * Mq * Cq;
    long long idx = (long long)blockIdx.x * blockDim.x + threadIdx.x;
    if (idx >= total) return;
    const int c = idx & (Cq - 1);
    long long r = idx >> 6;
    const int j = (int)(r % Mq); r /= Mq;
    const int w = (int)(r % nw);
    const int b = (int)(r / nw);
    const int win = j / Nq, n = j % Nq;
    const int t = w + win;
    dst[idx] = src[(((long long)b * Tt + t) * Nq + n) * Cq + c]
             + temb[t * Cq + c] + semb[n * Cq + c];
}

// ---------------------------------------------------------------------------
// Driver — R14 adjacency fork + bw-half pipelining of qkv/flash.
// ---------------------------------------------------------------------------
static inline dim3 fgrid(int M, int N, int batch)
{
    return dim3((N + 63) / 64, (M + 127) / 128, batch);
}

extern "C" void kernel_launch(void* const* d_in, const int* in_sizes, int n_in,
                              void* d_out, int out_size)
{
    (void)in_sizes; (void)n_in; (void)out_size;

    const float* x     = (const float*)d_in[0];
    const float* Wqkv  = (const float*)d_in[4];
    const float* bqkv  = (const float*)d_in[5];
    const float* Wlin  = (const float*)d_in[6];
    const float* blin  = (const float*)d_in[7];
    const float* Wa    = (const float*)d_in[8];
    const float* Wb    = (const float*)d_in[9];
    const float* temb0 = (const float*)d_in[13];
    const float* temb1 = (const float*)d_in[14];
    const float* semb  = (const float*)d_in[15];
    const float* Wo    = (const float*)d_in[16];
    const float* bo    = (const float*)d_in[17];
    float* out = (float*)d_out;

    float *cur, *qkv, *nA, *nB, *adj, *cand0, *cand1;
    cudaGetSymbolAddress((void**)&cur,   g_cur);
    cudaGetSymbolAddress((void**)&qkv,   g_qkv);
    cudaGetSymbolAddress((void**)&nA,    g_nA);
    cudaGetSymbolAddress((void**)&nB,    g_nB);
    cudaGetSymbolAddress((void**)&adj,   g_adj);
    cudaGetSymbolAddress((void**)&cand0, g_cand0);
    cudaGetSymbolAddress((void**)&cand1, g_cand1);

    cudaFuncSetAttribute(flash_attn,
        cudaFuncAttributeMaxDynamicSharedMemorySize, FA_SMEM_BYTES);

    cudaStream_t s2;
    cudaStreamCreateWithFlags(&s2, cudaStreamNonBlocking);
    cudaEvent_t evFork[6], evQ0[6], evAdj[6], evJoin[6];
    for (int i = 0; i < 6; ++i) {
        cudaEventCreateWithFlags(&evFork[i], cudaEventDisableTiming);
        cudaEventCreateWithFlags(&evQ0[i],   cudaEventDisableTiming);
        cudaEventCreateWithFlags(&evAdj[i],  cudaEventDisableTiming);
        cudaEventCreateWithFlags(&evJoin[i], cudaEventDisableTiming);
    }

    const float att_scale = 1.0f / sqrtf((float)ATTq);

    int fi = 0;
    for (int layer = 0; layer < 2; ++layer) {
        const int Tt = layer ? (Tq - 2) : Tq;
        const int nw = Tt - 2;
        const int BW = Bq * nw;
        const int BWh = BW / 2;                 // 20 / 16
        const float* src  = layer ? cand0 : x;
        const float* temb = layer ? temb1 : temb0;
        float* cand = layer ? cand1 : cand0;

        {
            const long long tot = (long long)BW * Mq * Cq;
            build_windows_kernel<<<(unsigned)((tot + 255) / 256), 256>>>(
                src, temb, semb, cur, nw, Tt);
        }

        for (int f = 0; f < 3; ++f, ++fi) {
            // fork: adjacency on s2
            cudaEventRecord(evFork[fi], 0);
            cudaStreamWaitEvent(s2, evFork[fi], 0);
            adj_rows_kernel<<<Mq / 4, 256, 0, s2>>>(cur, Wa, Wb, nA, nB, BW);
            adj_sigmoid<<<dim3(10, 38), 256, 0, s2>>>(nA, nB, adj);
            cudaEventRecord(evAdj[fi], s2);

            // qkv half 0 on main
            gemm_fast<false><<<fgrid(BWh * Mq, 3 * ATTq, 1), 128>>>(
                cur, Cq, 0, Wqkv, 3 * ATTq, 0, qkv, 3 * ATTq, 0,
                BWh * Mq, 3 * ATTq, Cq, bqkv, 1.f, 0);
            cudaEventRecord(evQ0[fi], 0);

            // flash half 0 on s2 (after adj, which is stream-ordered, + qkv0)
            cudaStreamWaitEvent(s2, evQ0[fi], 0);
            flash_attn<<<dim3((Mq + RQT - 1) / RQT, BWh), 256,
                         FA_SMEM_BYTES, s2>>>(
                qkv, adj, Wlin, blin, cur, cand, att_scale, f == 0 ? 1 : 2);
            cudaEventRecord(evJoin[fi], s2);

            // qkv half 1 on main (concurrent with flash half 0)
            gemm_fast<false><<<fgrid((BW - BWh) * Mq, 3 * ATTq, 1), 128>>>(
                cur + (long long)BWh * Mq * Cq, Cq, 0,
                Wqkv, 3 * ATTq, 0,
                qkv + (long long)BWh * Mq * 3 * ATTq, 3 * ATTq, 0,
                (BW - BWh) * Mq, 3 * ATTq, Cq, bqkv, 1.f, 0);

            // flash half 1 on main (needs adj from s2)
            cudaStreamWaitEvent(0, evAdj[fi], 0);
            flash_attn<<<dim3((Mq + RQT - 1) / RQT, BW - BWh), 256,
                         FA_SMEM_BYTES>>>(
                qkv + (long long)BWh * Mq * 384, adj, Wlin, blin,
                cur + (long long)BWh * Mq * Cq,
                cand + (long long)BWh * Nq * Cq,
                att_scale, f == 0 ? 1 : 2);

            // join: everything after needs flash half 0 too
            cudaStreamWaitEvent(0, evJoin[fi], 0);
        }
    }

    gemm_tail<<<fgrid(Bq * Nq, OUTFq, 1), 128>>>(cand1, Wo, bo, out);
}

// round 17
// speedup vs baseline: 1.0129x; 1.0129x over previous
#include <cuda_runtime.h>
#include <cuda_bf16.h>
#include <math.h>
#include <float.h>

#define Bq    4
#define Tq    12
#define Nq    200
#define Cq    64
#define ATTq  128
#define OUTFq 128
#define PREDq 12
#define Mq    600
#define BW0   40
#define BW1   32

enum { F_RELU = 1, F_RELUB = 2, F_SIGMOID = 4 };

__device__ float g_cur  [BW0 * Mq * Cq];
__device__ float g_qkv  [BW0 * Mq * 3 * ATTq];
__device__ float g_nA   [Mq * Cq];
__device__ float g_nB   [Mq * Cq];
__device__ float g_adj  [Mq * Mq];
__device__ float g_cand0[BW0 * Nq * Cq];
__device__ float g_cand1[BW1 * Nq * Cq];
__device__ float g_d    [Bq * Nq * 8 * Cq];
__device__ float g_o1   [Bq * Nq * OUTFq];

__device__ __forceinline__ float2 ffma2(float2 a, float2 b, float2 c)
{
    float2 d;
    asm("fma.rn.f32x2 %0, %1, %2, %3;"
        : "=l"(reinterpret_cast<unsigned long long&>(d))
        : "l"(reinterpret_cast<unsigned long long&>(a)),
          "l"(reinterpret_cast<unsigned long long&>(b)),
          "l"(reinterpret_cast<unsigned long long&>(c)));
    return d;
}

// ---------------------------------------------------------------------------
// Generic fast GEMM — exact R8 version.
// ---------------------------------------------------------------------------
template<bool TB>
__global__ void __launch_bounds__(128, 3)
gemm_fast(const float* __restrict__ A, int lda, long long aBS,
          const float* __restrict__ B, int ldb, long long bBS,
          float* __restrict__ Cm, int ldc, long long cBS,
          int M, int N, int K,
          const float* __restrict__ bias, float scale, int flags)
{
    __shared__ __align__(16) float  As[2][16][128];
    __shared__ __align__(16) float2 Bs[2][16][8][8];

    A  += (long long)blockIdx.z * aBS;
    B  += (long long)blockIdx.z * bBS;
    Cm += (long long)blockIdx.z * cBS;

    const int m0 = blockIdx.y * 128, n0 = blockIdx.x * 64;
    const int tid = threadIdx.x;
    const int tm = tid >> 3, tn = tid & 7;

    float2 acc[4][8];
    #pragma unroll
    for (int i = 0; i < 4; ++i)
        #pragma unroll
        for (int j = 0; j < 8; ++j) acc[i][j] = make_float2(0.f, 0.f);

    const int nk = (K + 15) >> 4;
    const bool relub = (flags & F_RELUB);
    float va[16], vb[8];

    auto loadA = [&](int k0) {
        const int gm = m0 + tid;
        if (gm < M) {
            const float* p = A + (long long)gm * lda + k0;
            if (k0 + 16 <= K) {
                const float4* q = (const float4*)p;
                float4 t0 = q[0], t1 = q[1], t2 = q[2], t3 = q[3];
                va[0]=t0.x; va[1]=t0.y; va[2]=t0.z; va[3]=t0.w;
                va[4]=t1.x; va[5]=t1.y; va[6]=t1.z; va[7]=t1.w;
                va[8]=t2.x; va[9]=t2.y; va[10]=t2.z; va[11]=t2.w;
                va[12]=t3.x; va[13]=t3.y; va[14]=t3.z; va[15]=t3.w;
            } else {
                #pragma unroll
                for (int t = 0; t < 16; ++t)
                    va[t] = (k0 + t < K) ? p[t] : 0.f;
            }
        } else {
            #pragma unroll
            for (int t = 0; t < 16; ++t) va[t] = 0.f;
        }
    };
    auto loadB = [&](int k0) {
        if (!TB) {
            const int kb = tid >> 3, nb = tid & 7;
            const int gk = k0 + kb, gn0 = n0 + nb * 8;
            if (gk < K) {
                const float* p = B + (long long)gk * ldb + gn0;
                if (gn0 + 8 <= N) {
                    const float4* q = (const float4*)p;
                    float4 t0 = q[0], t1 = q[1];
                    vb[0]=t0.x; vb[1]=t0.y; vb[2]=t0.z; vb[3]=t0.w;
                    vb[4]=t1.x; vb[5]=t1.y; vb[6]=t1.z; vb[7]=t1.w;
                } else {
                    #pragma unroll
                    for (int j = 0; j < 8; ++j)
                        vb[j] = (gn0 + j < N) ? p[j] : 0.f;
                }
            } else {
                #pragma unroll
                for (int j = 0; j < 8; ++j) vb[j] = 0.f;
            }
        } else {
            const int nl = tid >> 1, kh = (tid & 1) * 8;
            const int gn = n0 + nl, gk0 = k0 + kh;
            if (gn < N) {
                const float* p = B + (long long)gn * ldb + gk0;
                if (gk0 + 8 <= K) {
                    const float4* q = (const float4*)p;
                    float4 t0 = q[0], t1 = q[1];
                    vb[0]=t0.x; vb[1]=t0.y; vb[2]=t0.z; vb[3]=t0.w;
                    vb[4]=t1.x; vb[5]=t1.y; vb[6]=t1.z; vb[7]=t1.w;
                } else {
                    #pragma unroll
                    for (int t = 0; t < 8; ++t)
                        vb[t] = (gk0 + t < K) ? p[t] : 0.f;
                }
            } else {
                #pragma unroll
                for (int t = 0; t < 8; ++t) vb[t] = 0.f;
            }
        }
    };
    auto storeA = [&](int buf) {
        #pragma unroll
        for (int t = 0; t < 16; ++t) As[buf][t][tid] = va[t];
    };
    auto storeB = [&](int buf) {
        if (!TB) {
            const int kb = tid >> 3, nb = tid & 7;
            #pragma unroll
            for (int j = 0; j < 8; ++j) {
                float v = vb[j];
                if (relub) v = fmaxf(v, 0.f);
                Bs[buf][kb][j][nb] = make_float2(v, v);
            }
        } else {
            const int nl = tid >> 1, kh = (tid & 1) * 8;
            const int jj = nl & 7, tt = nl >> 3;
            #pragma unroll
            for (int t = 0; t < 8; ++t) {
                float v = vb[t];
                if (relub) v = fmaxf(v, 0.f);
                Bs[buf][kh + t][jj][tt] = make_float2(v, v);
            }
        }
    };

    int buf = 0;
    loadA(0); loadB(0);
    storeA(0); storeB(0);
    __syncthreads();

    for (int t = 0; t < nk; ++t) {
        if (t + 1 < nk) { loadA((t + 1) * 16); loadB((t + 1) * 16); }
        #pragma unroll
        for (int kk = 0; kk < 16; ++kk) {
            const float4* ap = (const float4*)(&As[buf][kk][0]) + tm * 2;
            float4 a0 = ap[0], a1 = ap[1];
            float2 a2[4];
            a2[0] = make_float2(a0.x, a0.y);
            a2[1] = make_float2(a0.z, a0.w);
            a2[2] = make_float2(a1.x, a1.y);
            a2[3] = make_float2(a1.z, a1.w);
            #pragma unroll
            for (int j = 0; j < 8; ++j) {
                float2 b2 = Bs[buf][kk][j][tn];
                #pragma unroll
                for (int i = 0; i < 4; ++i)
                    acc[i][j] = ffma2(a2[i], b2, acc[i][j]);
            }
        }
        if (t + 1 < nk) { buf ^= 1; storeA(buf); storeB(buf); }
        __syncthreads();
    }

    auto epi = [&](float v, int gn) {
        v *= scale;
        if (bias) v += bias[gn];
        if (flags & F_RELU) v = fmaxf(v, 0.f);
        if (flags & F_SIGMOID) v = 1.f / (1.f + __expf(-v));
        return v;
    };

    const int gn0 = n0 + tn * 8;
    const bool interior = (gn0 + 8 <= N) && (m0 + tm * 8 + 8 <= M);
    if (interior) {
        #pragma unroll
        for (int i = 0; i < 4; ++i)
            #pragma unroll
            for (int half = 0; half < 2; ++half) {
                const int gm = m0 + tm * 8 + 2 * i + half;
                float r[8];
                #pragma unroll
                for (int j = 0; j < 8; ++j)
                    r[j] = epi(half ? acc[i][j].y : acc[i][j].x, gn0 + j);
                float4* q = (float4*)(Cm + (long long)gm * ldc + gn0);
                q[0] = make_float4(r[0], r[1], r[2], r[3]);
                q[1] = make_float4(r[4], r[5], r[6], r[7]);
            }
    } else {
        #pragma unroll
        for (int i = 0; i < 4; ++i)
            #pragma unroll
            for (int half = 0; half < 2; ++half) {
                const int gm = m0 + tm * 8 + 2 * i + half;
                if (gm >= M) continue;
                #pragma unroll
                for (int j = 0; j < 8; ++j) {
                    const int gn = gn0 + j;
                    if (gn >= N) continue;
                    Cm[(long long)gm * ldc + gn] =
                        epi(half ? acc[i][j].y : acc[i][j].x, gn);
                }
            }
    }
}

// ---------------------------------------------------------------------------
// Fused flash attention — exact R8/R14 version.
// ---------------------------------------------------------------------------
#define RQT 96
#define FA_SMEM_BYTES (23424 * 4)

__global__ void __launch_bounds__(256, 2)
flash_attn(const float* __restrict__ qkv,
           const float* __restrict__ adj,
           const float* __restrict__ Wlin,
           const float* __restrict__ blin,
           float* __restrict__ curo,
           float* __restrict__ cand,
           float scale, int candmode)
{
    extern __shared__ float sm[];
    float*  Qs  = sm;
    float2* Ks  = (float2*)(sm + 12544);
    float2* Vs  = (float2*)(sm + 12544);
    float*  Ps  = sm + 16768;
    float*  At  = sm;
    float*  Wl  = sm + 12544;
    float*  m_s  = sm + 23040;
    float*  z_s  = m_s + RQT;
    float*  sa_s = z_s + RQT;
    float*  f_s  = sa_s + RQT;

    const int tid = threadIdx.x;
    const int bw  = blockIdx.y;
    const int r0  = blockIdx.x * RQT;
    const int tmA = tid >> 4, tnA = tid & 15;
    const int twB = tid >> 5, tnB = tid & 31;

    const float* qb = qkv + (long long)bw * Mq * 384;

    #pragma unroll
    for (int i = tid; i < 96 * 32; i += 256) {
        const int mq = i >> 5;
        const int kq = (i & 31) << 2;
        float4 v = make_float4(0.f, 0.f, 0.f, 0.f);
        if (r0 + mq < Mq)
            v = *(const float4*)(qb + (long long)(r0 + mq) * 384 + kq);
        Qs[(kq + 0) * 98 + mq] = v.x;
        Qs[(kq + 1) * 98 + mq] = v.y;
        Qs[(kq + 2) * 98 + mq] = v.z;
        Qs[(kq + 3) * 98 + mq] = v.w;
    }
    if (tid < RQT) { m_s[tid] = -FLT_MAX; z_s[tid] = 0.f; sa_s[tid] = 0.f; }

    float2 acc[6][4];
    #pragma unroll
    for (int i = 0; i < 6; ++i)
        #pragma unroll
        for (int j = 0; j < 4; ++j) acc[i][j] = make_float2(0.f, 0.f);

    const int bn = tid >> 2;
    const int kh = (tid & 3) << 2;

    __syncthreads();

    for (int ch = 0; ch < 10; ++ch) {
        const int n0 = ch * 64;

        float2 sA[3][4];
        #pragma unroll
        for (int p = 0; p < 3; ++p)
            #pragma unroll
            for (int j = 0; j < 4; ++j) sA[p][j] = make_float2(0.f, 0.f);

        {
            const int gn = n0 + bn;
            float4 kv = (gn < Mq)
                ? *(const float4*)(qb + (long long)gn * 384 + 128 + kh)
                : make_float4(0.f, 0.f, 0.f, 0.f);
            Ks[(kh + 0) * 66 + bn] = make_float2(kv.x, kv.x);
            Ks[(kh + 1) * 66 + bn] = make_float2(kv.y, kv.y);
            Ks[(kh + 2) * 66 + bn] = make_float2(kv.z, kv.z);
            Ks[(kh + 3) * 66 + bn] = make_float2(kv.w, kv.w);
        }
        __syncthreads();

        #pragma unroll
        for (int s = 0; s < 8; ++s) {
            float4 kv = make_float4(0.f, 0.f, 0.f, 0.f);
            if (s < 7) {
                const int gn = n0 + bn;
                if (gn < Mq)
                    kv = *(const float4*)(qb + (long long)gn * 384 + 128
                                          + (s + 1) * 16 + kh);
            }
            const float2* kbuf = Ks + (s & 1) * (16 * 66);
            const int kq0 = s * 16;
            #pragma unroll
            for (int kk = 0; kk < 16; ++kk) {
                const float2* ap = (const float2*)(Qs + (kq0 + kk) * 98 + 6 * tmA);
                const float2 a0 = ap[0], a1 = ap[1], a2 = ap[2];
                #pragma unroll
                for (int j = 0; j < 4; ++j) {
                    const float2 b = kbuf[kk * 66 + tnA + 16 * j];
                    sA[0][j] = ffma2(a0, b, sA[0][j]);
                    sA[1][j] = ffma2(a1, b, sA[1][j]);
                    sA[2][j] = ffma2(a2, b, sA[2][j]);
                }
            }
            if (s < 7) {
                float2* kdst = Ks + ((s + 1) & 1) * (16 * 66);
                kdst[(kh + 0) * 66 + bn] = make_float2(kv.x, kv.x);
                kdst[(kh + 1) * 66 + bn] = make_float2(kv.y, kv.y);
                kdst[(kh + 2) * 66 + bn] = make_float2(kv.z, kv.z);
                kdst[(kh + 3) * 66 + bn] = make_float2(kv.w, kv.w);
            }
            __syncthreads();
        }

        #pragma unroll
        for (int p = 0; p < 3; ++p) {
            const int r = 6 * tmA + 2 * p;
            float2 sv[4];
            #pragma unroll
            for (int j = 0; j < 4; ++j) {
                const int gn = n0 + tnA + 16 * j;
                if (gn < Mq) {
                    sv[j].x = sA[p][j].x * scale;
                    sv[j].y = sA[p][j].y * scale;
                } else { sv[j].x = -FLT_MAX; sv[j].y = -FLT_MAX; }
            }
            float mxx = fmaxf(fmaxf(sv[0].x, sv[1].x), fmaxf(sv[2].x, sv[3].x));
            float mxy = fmaxf(fmaxf(sv[0].y, sv[1].y), fmaxf(sv[2].y, sv[3].y));
            #pragma unroll
            for (int w = 8; w; w >>= 1) {
                mxx = fmaxf(mxx, __shfl_xor_sync(0xffffffffu, mxx, w));
                mxy = fmaxf(mxy, __shfl_xor_sync(0xffffffffu, mxy, w));
            }
            const float mox = m_s[r], moy = m_s[r + 1];
            const float mnx = fmaxf(mox, mxx), mny = fmaxf(moy, mxy);
            const float fx = __expf(mox - mnx), fy = __expf(moy - mny);

            const int grx = r0 + r, gry = grx + 1;
            float zex = 0.f, zey = 0.f, saex = 0.f, saey = 0.f;
            #pragma unroll
            for (int j = 0; j < 4; ++j) {
                const int gn = n0 + tnA + 16 * j;
                const float ex = __expf(sv[j].x - mnx);
                const float ey = __expf(sv[j].y - mny);
                float ax = 0.f, ay = 0.f;
                if (gn < Mq) {
                    if (grx < Mq) ax = adj[(long long)grx * Mq + gn];
                    if (gry < Mq) ay = adj[(long long)gry * Mq + gn];
                }
                const float px = ex * ax, py = ey * ay;
                zex += ex; zey += ey; saex += px; saey += py;
                *(float2*)&Ps[(tnA + 16 * j) * 98 + r] = make_float2(px, py);
            }
            #pragma unroll
            for (int w = 8; w; w >>= 1) {
                zex  += __shfl_xor_sync(0xffffffffu, zex,  w);
                zey  += __shfl_xor_sync(0xffffffffu, zey,  w);
                saex += __shfl_xor_sync(0xffffffffu, saex, w);
                saey += __shfl_xor_sync(0xffffffffu, saey, w);
            }
            if (tnA == 0) {
                z_s[r]      = z_s[r]      * fx + zex;
                z_s[r + 1]  = z_s[r + 1]  * fy + zey;
                sa_s[r]     = sa_s[r]     * fx + saex;
                sa_s[r + 1] = sa_s[r + 1] * fy + saey;
                m_s[r] = mnx; m_s[r + 1] = mny;
                f_s[r] = fx;  f_s[r + 1] = fy;
            }
        }
        __syncthreads();

        #pragma unroll
        for (int i = 0; i < 6; ++i) {
            const int r = 12 * twB + 2 * i;
            const float2 f2 = *(const float2*)&f_s[r];
            #pragma unroll
            for (int j = 0; j < 4; ++j) {
                acc[i][j].x *= f2.x; acc[i][j].y *= f2.y;
            }
        }

        #pragma unroll
        for (int vs = 0; vs < 4; ++vs) {
            #pragma unroll
            for (int rr = 0; rr < 2; ++rr) {
                const int n = rr * 8 + twB;
                const int gn = n0 + vs * 16 + n;
                #pragma unroll
                for (int s4 = 0; s4 < 4; ++s4) {
                    const int c = tnB + 32 * s4;
                    const float v = (gn < Mq)
                        ? fmaxf(qb[(long long)gn * 384 + 256 + c], 0.f) : 0.f;
                    Vs[n * 132 + tnB + 32 * s4] = make_float2(v, v);
                }
            }
            __syncthreads();
            #pragma unroll
            for (int nn = 0; nn < 16; ++nn) {
                const int n = vs * 16 + nn;
                const float2* prow = (const float2*)&Ps[n * 98 + 12 * twB];
                const float2 p0 = prow[0], p1 = prow[1], p2 = prow[2],
                             p3 = prow[3], p4 = prow[4], p5 = prow[5];
                #pragma unroll
                for (int j = 0; j < 4; ++j) {
                    const float2 b = Vs[nn * 132 + tnB + 32 * j];
                    acc[0][j] = ffma2(p0, b, acc[0][j]);
                    acc[1][j] = ffma2(p1, b, acc[1][j]);
                    acc[2][j] = ffma2(p2, b, acc[2][j]);
                    acc[3][j] = ffma2(p3, b, acc[3][j]);
                    acc[4][j] = ffma2(p4, b, acc[4][j]);
                    acc[5][j] = ffma2(p5, b, acc[5][j]);
                }
            }
            __syncthreads();
        }
    }

    // ---- fused epilogue: cur = att @ Wlin + blin ----
    #pragma unroll
    for (int i = 0; i < 6; ++i) {
        const int r = 12 * twB + 2 * i;
        #pragma unroll
        for (int h = 0; h < 2; ++h) {
            const int row = r + h;
            const float sa = sa_s[row], zz = z_s[row];
            const float inv = (sa > 0.f) ? 1.f / (sa + 1e-8f * zz) : 0.f;
            #pragma unroll
            for (int j = 0; j < 4; ++j) {
                const int c = tnB + 32 * j;
                At[c * 98 + row] = (h ? acc[i][j].y : acc[i][j].x) * inv;
            }
        }
    }
    #pragma unroll
    for (int i = tid; i < 128 * 16; i += 256) {
        const int k = i >> 4;
        const int c4 = (i & 15) << 2;
        const float4 w = *(const float4*)(Wlin + k * 64 + c4);
        Wl[k * 66 + c4 + 0] = w.x;
        Wl[k * 66 + c4 + 1] = w.y;
        Wl[k * 66 + c4 + 2] = w.z;
        Wl[k * 66 + c4 + 3] = w.w;
    }
    __syncthreads();

    {
        const int lane = tid & 31;
        const int c0 = lane * 2;
        const int rbase = 12 * twB;
        float2 o0[6], o1[6];
        #pragma unroll
        for (int p = 0; p < 6; ++p) {
            o0[p] = make_float2(0.f, 0.f);
            o1[p] = make_float2(0.f, 0.f);
        }
        #pragma unroll 4
        for (int k = 0; k < 128; ++k) {
            const float2* arow = (const float2*)(At + k * 98 + rbase);
            const float2 bv = *(const float2*)(Wl + k * 66 + c0);
            const float2 b0 = make_float2(bv.x, bv.x);
            const float2 b1 = make_float2(bv.y, bv.y);
            #pragma unroll
            for (int p = 0; p < 6; ++p) {
                const float2 a = arow[p];
                o0[p] = ffma2(a, b0, o0[p]);
                o1[p] = ffma2(a, b1, o1[p]);
            }
        }
        const float bl0 = blin[c0], bl1 = blin[c0 + 1];
        #pragma unroll
        for (int p = 0; p < 6; ++p) {
            #pragma unroll
            for (int h = 0; h < 2; ++h) {
                const int gq = r0 + rbase + 2 * p + h;
                if (gq >= Mq) continue;
                const float v0 = (h ? o0[p].y : o0[p].x) + bl0;
                const float v1 = (h ? o1[p].y : o1[p].x) + bl1;
                float* cp = curo + ((long long)bw * Mq + gq) * Cq + c0;
                *(float2*)cp = make_float2(v0, v1);
                if (gq >= 2 * Nq) {
                    float* kp = cand + ((long long)(bw * Nq + (gq - 2 * Nq)) * Cq) + c0;
                    if (candmode == 1)
                        *(float2*)kp = make_float2(v0, v1);
                    else {
                        float2 c2 = *(float2*)kp;
                        *(float2*)kp = make_float2(fmaxf(c2.x, v0),
                                                   fmaxf(c2.y, v1));
                    }
                }
            }
        }
    }
}

// ---------------------------------------------------------------------------
// adjacency
// ---------------------------------------------------------------------------
__global__ void __launch_bounds__(256)
adj_rows_kernel(const float* __restrict__ cur,
                const float* __restrict__ Wa,
                const float* __restrict__ Wb,
                float* __restrict__ nA,
                float* __restrict__ nB, int BW)
{
    __shared__ float node_s[4][Cq];
    const int tid = threadIdx.x;
    const int mi = tid >> 6, c = tid & 63;
    const int m = blockIdx.x * 4 + mi;
    float s = 0.f;
    for (int bw = 0; bw < BW; ++bw)
        s += cur[((long long)bw * Mq + m) * Cq + c];
    node_s[mi][c] = s / (float)BW;
    __syncthreads();
    float a = 0.f, b = 0.f;
    #pragma unroll
    for (int k = 0; k < Cq; ++k) {
        const float nv = node_s[mi][k];
        a = fmaf(nv, Wa[k * Cq + c], a);
        b = fmaf(nv, Wb[k * Cq + c], b);
    }
    nA[m * Cq + c] = a;
    nB[m * Cq + c] = b;
}

__global__ void __launch_bounds__(256)
adj_sigmoid(const float* __restrict__ nA, const float* __restrict__ nB,
            float* __restrict__ adj)
{
    __shared__ float a_s[16][Cq];
    __shared__ float b_s[64][Cq + 1];
    const int r0 = blockIdx.y * 16, n0 = blockIdx.x * 64;
    const int tid = threadIdx.x;

    #pragma unroll
    for (int i = tid; i < 16 * Cq; i += 256) {
        const int r = i >> 6, k = i & 63;
        a_s[r][k] = (r0 + r < Mq) ? nA[(r0 + r) * Cq + k] : 0.f;
    }
    #pragma unroll
    for (int i = tid; i < 64 * Cq; i += 256) {
        const int n = i >> 6, k = i & 63;
        b_s[n][k] = (n0 + n < Mq) ? nB[(n0 + n) * Cq + k] : 0.f;
    }
    __syncthreads();

    const int tr = tid >> 6;
    const int tc = tid & 63;
    #pragma unroll
    for (int rr = 0; rr < 4; ++rr) {
        const int r = tr * 4 + rr;
        float s = 0.f;
        #pragma unroll
        for (int k = 0; k < Cq; ++k)
            s = fmaf(a_s[r][k], b_s[tc][k], s);
        const int gr = r0 + r, gn = n0 + tc;
        if (gr < Mq && gn < Mq)
            adj[(long long)gr * Mq + gn] = 1.f / (1.f + __expf(-s * 0.125f));
    }
}

// ---------------------------------------------------------------------------
// Elementwise helpers
// ---------------------------------------------------------------------------
__global__ void build_windows_kernel(const float* __restrict__ src,
                                     const float* __restrict__ temb,
                                     const float* __restrict__ semb,
                                     float* __restrict__ dst,
                                     int nw, int Tt)
{
    const long long total = (long long)Bq * nw * Mq * Cq;
    long long idx = (long long)blockIdx.x * blockDim.x + threadIdx.x;
    if (idx >= total) return;
    const int c = idx & (Cq - 1);
    long long r = idx >> 6;
    const int j = (int)(r % Mq); r /= Mq;
    const int w = (int)(r % nw);
    const int b = (int)(r / nw);
    const int win = j / Nq, n = j % Nq;
    const int t = w + win;
    dst[idx] = src[(((long long)b * Tt + t) * Nq + n) * Cq + c]
             + temb[t * Cq + c] + semb[n * Cq + c];
}

__global__ void transp_kernel(const float* __restrict__ h,
                              float* __restrict__ d)
{
    const int total = Bq * Nq * 8 * Cq;
    const int idx = blockIdx.x * blockDim.x + threadIdx.x;
    if (idx >= total) return;
    const int f = idx & (Cq - 1);
    int r = idx >> 6;
    const int t = r % 8; r /= 8;
    const int n = r % Nq;
    const int b = r / Nq;
    d[idx] = h[(((long long)b * 8 + t) * Nq + n) * Cq + f];
}

__global__ void tile_kernel(const float* __restrict__ o1,
                            float* __restrict__ out)
{
    const int total = Bq * PREDq * Nq * OUTFq;
    const int idx = blockIdx.x * blockDim.x + threadIdx.x;
    if (idx >= total) return;
    const int f = idx & (OUTFq - 1);
    int r = idx >> 7;
    const int row = r % (PREDq * Nq);
    const int b = r / (PREDq * Nq);
    const int n = row % Nq;
    out[idx] = o1[((long long)b * Nq + n) * OUTFq + f];
}

// ---------------------------------------------------------------------------
// Driver — adjacency chain forked onto a side stream, overlapped with qkv.
// ---------------------------------------------------------------------------
static inline dim3 fgrid(int M, int N, int batch)
{
    return dim3((N + 63) / 64, (M + 127) / 128, batch);
}

extern "C" void kernel_launch(void* const* d_in, const int* in_sizes, int n_in,
                              void* d_out, int out_size)
{
    (void)in_sizes; (void)n_in; (void)out_size;

    const float* x     = (const float*)d_in[0];
    const float* Wqkv  = (const float*)d_in[4];
    const float* bqkv  = (const float*)d_in[5];
    const float* Wlin  = (const float*)d_in[6];
    const float* blin  = (const float*)d_in[7];
    const float* Wa    = (const float*)d_in[8];
    const float* Wb    = (const float*)d_in[9];
    const float* temb0 = (const float*)d_in[13];
    const float* temb1 = (const float*)d_in[14];
    const float* semb  = (const float*)d_in[15];
    const float* Wo    = (const float*)d_in[16];
    const float* bo    = (const float*)d_in[17];
    float* out = (float*)d_out;

    float *cur, *qkv, *nA, *nB, *adj, *cand0, *cand1, *dbuf, *o1;
    cudaGetSymbolAddress((void**)&cur,   g_cur);
    cudaGetSymbolAddress((void**)&qkv,   g_qkv);
    cudaGetSymbolAddress((void**)&nA,    g_nA);
    cudaGetSymbolAddress((void**)&nB,    g_nB);
    cudaGetSymbolAddress((void**)&adj,   g_adj);
    cudaGetSymbolAddress((void**)&cand0, g_cand0);
    cudaGetSymbolAddress((void**)&cand1, g_cand1);
    cudaGetSymbolAddress((void**)&dbuf,  g_d);
    cudaGetSymbolAddress((void**)&o1,    g_o1);

    cudaFuncSetAttribute(flash_attn,
        cudaFuncAttributeMaxDynamicSharedMemorySize, FA_SMEM_BYTES);

    cudaStream_t s2;
    cudaStreamCreateWithFlags(&s2, cudaStreamNonBlocking);
    cudaEvent_t evFork[6], evJoin[6];
    for (int i = 0; i < 6; ++i) {
        cudaEventCreateWithFlags(&evFork[i], cudaEventDisableTiming);
        cudaEventCreateWithFlags(&evJoin[i], cudaEventDisableTiming);
    }

    const float att_scale = 1.0f / sqrtf((float)ATTq);

    int fi = 0;
    for (int layer = 0; layer < 2; ++layer) {
        const int Tt = layer ? (Tq - 2) : Tq;
        const int nw = Tt - 2;
        const int BW = Bq * nw;
        const float* src  = layer ? cand0 : x;
        const float* temb = layer ? temb1 : temb0;
        float* cand = layer ? cand1 : cand0;

        {
            const long long tot = (long long)BW * Mq * Cq;
            build_windows_kernel<<<(unsigned)((tot + 255) / 256), 256>>>(
                src, temb, semb, cur, nw, Tt);
        }

        for (int f = 0; f < 3; ++f, ++fi) {
            cudaEventRecord(evFork[fi], 0);
            cudaStreamWaitEvent(s2, evFork[fi], 0);
            adj_rows_kernel<<<Mq / 4, 256, 0, s2>>>(cur, Wa, Wb, nA, nB, BW);
            adj_sigmoid<<<dim3(10, 38), 256, 0, s2>>>(nA, nB, adj);
            cudaEventRecord(evJoin[fi], s2);

            gemm_fast<false><<<fgrid(BW * Mq, 3 * ATTq, 1), 128>>>(
                cur, Cq, 0, Wqkv, 3 * ATTq, 0, qkv, 3 * ATTq, 0,
                BW * Mq, 3 * ATTq, Cq, bqkv, 1.f, 0);

            cudaStreamWaitEvent(0, evJoin[fi], 0);

            flash_attn<<<dim3((Mq + RQT - 1) / RQT, BW), 256, FA_SMEM_BYTES>>>(
                qkv, adj, Wlin, blin, cur, cand, att_scale, f == 0 ? 1 : 2);
        }
    }

    {
        const int tot = Bq * Nq * 8 * Cq;
        transp_kernel<<<(tot + 255) / 256, 256>>>(cand1, dbuf);
    }
    gemm_fast<false><<<fgrid(Bq * Nq, OUTFq, 1), 128>>>(
        dbuf, 8 * Cq, 0, Wo, OUTFq, 0, o1, OUTFq, 0,
        Bq * Nq, OUTFq, 8 * Cq, bo, 1.f, F_RELU);
    {
        const int tot = Bq * PREDq * Nq * OUTFq;
        tile_kernel<<<(tot + 255) / 256, 256>>>(o1, out);
    }
}